// round 1
// baseline (speedup 1.0000x reference)
#include <cuda_runtime.h>
#include <cuda_bf16.h>

#define D_FEAT 128
#define D4 (D_FEAT / 4)          // 32 float4 per row
#define THREADS 512
#define ROWGROUPS (THREADS / D4) // 16
#define EPS 1e-6f

__global__ __launch_bounds__(THREADS, 2)
void graphnorm_kernel(const float4* __restrict__ x,
                      const int*    __restrict__ n_node,
                      const float4* __restrict__ mean_scale,
                      const float4* __restrict__ scale,
                      const float4* __restrict__ bias,
                      float4* __restrict__ out,
                      int nodes_per_graph)
{
    const int g     = blockIdx.x;
    const int t     = threadIdx.x;
    const int lane4 = t & (D4 - 1);   // which float4 column (0..31)
    const int rg    = t >> 5;         // row group (0..15)

    const float4* xg = x   + (size_t)g * nodes_per_graph * D4;
    float4*       og = out + (size_t)g * nodes_per_graph * D4;

    // ---- pass 1: accumulate sum and sum-of-squares per feature lane ----
    float4 s  = make_float4(0.f, 0.f, 0.f, 0.f);
    float4 s2 = make_float4(0.f, 0.f, 0.f, 0.f);
    for (int r = rg; r < nodes_per_graph; r += ROWGROUPS) {
        float4 v = xg[(size_t)r * D4 + lane4];
        s.x += v.x; s.y += v.y; s.z += v.z; s.w += v.w;
        s2.x = fmaf(v.x, v.x, s2.x);
        s2.y = fmaf(v.y, v.y, s2.y);
        s2.z = fmaf(v.z, v.z, s2.z);
        s2.w = fmaf(v.w, v.w, s2.w);
    }

    __shared__ float4 sh_s [ROWGROUPS][D4];
    __shared__ float4 sh_s2[ROWGROUPS][D4];
    sh_s [rg][lane4] = s;
    sh_s2[rg][lane4] = s2;
    __syncthreads();

    // tree-reduce the 16 row-group partials per column
    #pragma unroll
    for (int step = ROWGROUPS / 2; step >= 1; step >>= 1) {
        if (rg < step) {
            float4 a = sh_s[rg][lane4],  b = sh_s[rg + step][lane4];
            a.x += b.x; a.y += b.y; a.z += b.z; a.w += b.w;
            sh_s[rg][lane4] = a;
            float4 c = sh_s2[rg][lane4], d = sh_s2[rg + step][lane4];
            c.x += d.x; c.y += d.y; c.z += d.z; c.w += d.w;
            sh_s2[rg][lane4] = c;
        }
        __syncthreads();
    }

    // ---- per-feature constants (every thread computes for its lane4) ----
    const float inv_n = 1.0f / (float)n_node[g];
    float4 tot  = sh_s [0][lane4];
    float4 tot2 = sh_s2[0][lane4];
    float4 ms = __ldg(&mean_scale[lane4]);
    float4 sc = __ldg(&scale[lane4]);
    float4 bi = __ldg(&bias[lane4]);

    float4 mul, add;
    {
        // per component: mean = tot/n; m = mean*ms;
        // var = tot2/n - 2*m*mean + m*m; mul = rsqrt(var+eps)*sc; add = bi - m*mul
        float mean, m, var;
        mean = tot.x * inv_n; m = mean * ms.x;
        var  = tot2.x * inv_n - 2.0f * m * mean + m * m;
        mul.x = rsqrtf(var + EPS) * sc.x; add.x = bi.x - m * mul.x;

        mean = tot.y * inv_n; m = mean * ms.y;
        var  = tot2.y * inv_n - 2.0f * m * mean + m * m;
        mul.y = rsqrtf(var + EPS) * sc.y; add.y = bi.y - m * mul.y;

        mean = tot.z * inv_n; m = mean * ms.z;
        var  = tot2.z * inv_n - 2.0f * m * mean + m * m;
        mul.z = rsqrtf(var + EPS) * sc.z; add.z = bi.z - m * mul.z;

        mean = tot.w * inv_n; m = mean * ms.w;
        var  = tot2.w * inv_n - 2.0f * m * mean + m * m;
        mul.w = rsqrtf(var + EPS) * sc.w; add.w = bi.w - m * mul.w;
    }

    // ---- pass 2: y = x*mul + add (second read should hit L2) ----
    for (int r = rg; r < nodes_per_graph; r += ROWGROUPS) {
        float4 v = xg[(size_t)r * D4 + lane4];
        float4 y;
        y.x = fmaf(v.x, mul.x, add.x);
        y.y = fmaf(v.y, mul.y, add.y);
        y.z = fmaf(v.z, mul.z, add.z);
        y.w = fmaf(v.w, mul.w, add.w);
        og[(size_t)r * D4 + lane4] = y;
    }
}

extern "C" void kernel_launch(void* const* d_in, const int* in_sizes, int n_in,
                              void* d_out, int out_size)
{
    const float* x          = (const float*)d_in[0];
    const int*   n_node     = (const int*)d_in[1];
    const float* mean_scale = (const float*)d_in[2];
    const float* scale      = (const float*)d_in[3];
    const float* bias       = (const float*)d_in[4];
    float*       out        = (float*)d_out;

    const int n_graph = in_sizes[1];
    const int total_nodes = in_sizes[0] / D_FEAT;
    const int nodes_per_graph = total_nodes / n_graph;

    graphnorm_kernel<<<n_graph, THREADS>>>(
        (const float4*)x, n_node,
        (const float4*)mean_scale, (const float4*)scale, (const float4*)bias,
        (float4*)out, nodes_per_graph);
}

// round 4
// speedup vs baseline: 1.3903x; 1.3903x over previous
#include <cuda_runtime.h>
#include <cuda_bf16.h>

#define D_FEAT 128
#define D4 (D_FEAT / 4)      // 32 float4 per row
#define EPS 1e-6f

// ---------------- fast path: nodes_per_graph == 512 -------------------------
// One CTA = one (graph, 32-feature chunk). 256 threads, each thread caches
// 16 float4 in registers; single DRAM read + single DRAM write.
#define CHUNK4   8           // float4 columns per chunk (32 features)
#define FTHREADS 256
#define RG_FAST  (FTHREADS / CHUNK4)   // 32 row groups
#define ITERS    16                    // 512 / 32

__global__ __launch_bounds__(FTHREADS, 2)
void graphnorm_fast(const float4* __restrict__ x,
                    const int*    __restrict__ n_node,
                    const float4* __restrict__ mean_scale,
                    const float4* __restrict__ scale,
                    const float4* __restrict__ bias,
                    float4* __restrict__ out)
{
    const int b     = blockIdx.x;
    const int g     = b >> 2;           // graph
    const int chunk = b & 3;            // which 32-feature chunk
    const int t     = threadIdx.x;
    const int c     = t & (CHUNK4 - 1); // column within chunk (0..7)
    const int rg    = t >> 3;           // row group (0..31)
    const int col4  = chunk * CHUNK4 + c;   // global float4 column

    const size_t base = (size_t)g * 512 * D4 + col4;
    const float4* xg = x   + base;
    float4*       og = out + base;

    // ---- load 16 rows into registers, accumulate sum / sumsq ----
    float4 v[ITERS];
    float4 s  = make_float4(0.f, 0.f, 0.f, 0.f);
    float4 s2 = make_float4(0.f, 0.f, 0.f, 0.f);
    #pragma unroll
    for (int i = 0; i < ITERS; i++) {
        v[i] = xg[(size_t)(rg + i * RG_FAST) * D4];
    }
    #pragma unroll
    for (int i = 0; i < ITERS; i++) {
        s.x += v[i].x; s.y += v[i].y; s.z += v[i].z; s.w += v[i].w;
        s2.x = fmaf(v[i].x, v[i].x, s2.x);
        s2.y = fmaf(v[i].y, v[i].y, s2.y);
        s2.z = fmaf(v[i].z, v[i].z, s2.z);
        s2.w = fmaf(v[i].w, v[i].w, s2.w);
    }

    // ---- intra-warp reduce: threads sharing a column are lanes c,c+8,c+16,c+24
    #pragma unroll
    for (int m = 8; m <= 16; m <<= 1) {
        s.x  += __shfl_xor_sync(0xffffffffu, s.x,  m);
        s.y  += __shfl_xor_sync(0xffffffffu, s.y,  m);
        s.z  += __shfl_xor_sync(0xffffffffu, s.z,  m);
        s.w  += __shfl_xor_sync(0xffffffffu, s.w,  m);
        s2.x += __shfl_xor_sync(0xffffffffu, s2.x, m);
        s2.y += __shfl_xor_sync(0xffffffffu, s2.y, m);
        s2.z += __shfl_xor_sync(0xffffffffu, s2.z, m);
        s2.w += __shfl_xor_sync(0xffffffffu, s2.w, m);
    }

    // ---- cross-warp reduce via tiny smem (8 warps x 8 columns) ----
    __shared__ float4 sh_s [8][CHUNK4];
    __shared__ float4 sh_s2[8][CHUNK4];
    const int w = t >> 5;
    if ((t & 31) < CHUNK4) {            // lane 0..7 holds the warp partial
        sh_s [w][t & 7] = s;
        sh_s2[w][t & 7] = s2;
    }
    __syncthreads();

    float4 tot  = sh_s [0][c];
    float4 tot2 = sh_s2[0][c];
    #pragma unroll
    for (int k = 1; k < 8; k++) {
        float4 a = sh_s[k][c], b2 = sh_s2[k][c];
        tot.x  += a.x;  tot.y  += a.y;  tot.z  += a.z;  tot.w  += a.w;
        tot2.x += b2.x; tot2.y += b2.y; tot2.z += b2.z; tot2.w += b2.w;
    }

    // ---- per-feature constants ----
    const float inv_n = 1.0f / (float)n_node[g];
    float4 ms = __ldg(&mean_scale[col4]);
    float4 sc = __ldg(&scale[col4]);
    float4 bi = __ldg(&bias[col4]);

    float4 mul, add;
    {
        float mean, m, var;
        mean = tot.x * inv_n; m = mean * ms.x;
        var  = tot2.x * inv_n - 2.0f * m * mean + m * m;
        mul.x = rsqrtf(var + EPS) * sc.x; add.x = bi.x - m * mul.x;

        mean = tot.y * inv_n; m = mean * ms.y;
        var  = tot2.y * inv_n - 2.0f * m * mean + m * m;
        mul.y = rsqrtf(var + EPS) * sc.y; add.y = bi.y - m * mul.y;

        mean = tot.z * inv_n; m = mean * ms.z;
        var  = tot2.z * inv_n - 2.0f * m * mean + m * m;
        mul.z = rsqrtf(var + EPS) * sc.z; add.z = bi.z - m * mul.z;

        mean = tot.w * inv_n; m = mean * ms.w;
        var  = tot2.w * inv_n - 2.0f * m * mean + m * m;
        mul.w = rsqrtf(var + EPS) * sc.w; add.w = bi.w - m * mul.w;
    }

    // ---- write y straight from registers ----
    #pragma unroll
    for (int i = 0; i < ITERS; i++) {
        float4 y;
        y.x = fmaf(v[i].x, mul.x, add.x);
        y.y = fmaf(v[i].y, mul.y, add.y);
        y.z = fmaf(v[i].z, mul.z, add.z);
        y.w = fmaf(v[i].w, mul.w, add.w);
        og[(size_t)(rg + i * RG_FAST) * D4] = y;
    }
}

// ---------------- generic fallback (two-pass, any nodes_per_graph) ----------
#define GTHREADS 512
#define GROWGROUPS (GTHREADS / D4)

__global__ __launch_bounds__(GTHREADS, 2)
void graphnorm_generic(const float4* __restrict__ x,
                       const int*    __restrict__ n_node,
                       const float4* __restrict__ mean_scale,
                       const float4* __restrict__ scale,
                       const float4* __restrict__ bias,
                       float4* __restrict__ out,
                       int nodes_per_graph)
{
    const int g     = blockIdx.x;
    const int t     = threadIdx.x;
    const int lane4 = t & (D4 - 1);
    const int rg    = t >> 5;

    const float4* xg = x   + (size_t)g * nodes_per_graph * D4;
    float4*       og = out + (size_t)g * nodes_per_graph * D4;

    float4 s  = make_float4(0.f, 0.f, 0.f, 0.f);
    float4 s2 = make_float4(0.f, 0.f, 0.f, 0.f);
    for (int r = rg; r < nodes_per_graph; r += GROWGROUPS) {
        float4 v = xg[(size_t)r * D4 + lane4];
        s.x += v.x; s.y += v.y; s.z += v.z; s.w += v.w;
        s2.x = fmaf(v.x, v.x, s2.x);
        s2.y = fmaf(v.y, v.y, s2.y);
        s2.z = fmaf(v.z, v.z, s2.z);
        s2.w = fmaf(v.w, v.w, s2.w);
    }

    __shared__ float4 sh_s [GROWGROUPS][D4];
    __shared__ float4 sh_s2[GROWGROUPS][D4];
    sh_s [rg][lane4] = s;
    sh_s2[rg][lane4] = s2;
    __syncthreads();

    #pragma unroll
    for (int step = GROWGROUPS / 2; step >= 1; step >>= 1) {
        if (rg < step) {
            float4 a = sh_s[rg][lane4],  b = sh_s[rg + step][lane4];
            a.x += b.x; a.y += b.y; a.z += b.z; a.w += b.w;
            sh_s[rg][lane4] = a;
            float4 cc = sh_s2[rg][lane4], d = sh_s2[rg + step][lane4];
            cc.x += d.x; cc.y += d.y; cc.z += d.z; cc.w += d.w;
            sh_s2[rg][lane4] = cc;
        }
        __syncthreads();
    }

    const float inv_n = 1.0f / (float)n_node[g];
    float4 tot  = sh_s [0][lane4];
    float4 tot2 = sh_s2[0][lane4];
    float4 ms = __ldg(&mean_scale[lane4]);
    float4 sc = __ldg(&scale[lane4]);
    float4 bi = __ldg(&bias[lane4]);

    float4 mul, add;
    {
        float mean, m, var;
        mean = tot.x * inv_n; m = mean * ms.x;
        var  = tot2.x * inv_n - 2.0f * m * mean + m * m;
        mul.x = rsqrtf(var + EPS) * sc.x; add.x = bi.x - m * mul.x;

        mean = tot.y * inv_n; m = mean * ms.y;
        var  = tot2.y * inv_n - 2.0f * m * mean + m * m;
        mul.y = rsqrtf(var + EPS) * sc.y; add.y = bi.y - m * mul.y;

        mean = tot.z * inv_n; m = mean * ms.z;
        var  = tot2.z * inv_n - 2.0f * m * mean + m * m;
        mul.z = rsqrtf(var + EPS) * sc.z; add.z = bi.z - m * mul.z;

        mean = tot.w * inv_n; m = mean * ms.w;
        var  = tot2.w * inv_n - 2.0f * m * mean + m * m;
        mul.w = rsqrtf(var + EPS) * sc.w; add.w = bi.w - m * mul.w;
    }

    for (int r = rg; r < nodes_per_graph; r += GROWGROUPS) {
        float4 v = xg[(size_t)r * D4 + lane4];
        float4 y;
        y.x = fmaf(v.x, mul.x, add.x);
        y.y = fmaf(v.y, mul.y, add.y);
        y.z = fmaf(v.z, mul.z, add.z);
        y.w = fmaf(v.w, mul.w, add.w);
        og[(size_t)r * D4 + lane4] = y;
    }
}

extern "C" void kernel_launch(void* const* d_in, const int* in_sizes, int n_in,
                              void* d_out, int out_size)
{
    const float* x          = (const float*)d_in[0];
    const int*   n_node     = (const int*)d_in[1];
    const float* mean_scale = (const float*)d_in[2];
    const float* scale      = (const float*)d_in[3];
    const float* bias       = (const float*)d_in[4];
    float*       out        = (float*)d_out;

    const int n_graph = in_sizes[1];
    const int total_nodes = in_sizes[0] / D_FEAT;
    const int nodes_per_graph = total_nodes / n_graph;

    if (nodes_per_graph == 512) {
        graphnorm_fast<<<n_graph * 4, FTHREADS>>>(
            (const float4*)x, n_node,
            (const float4*)mean_scale, (const float4*)scale, (const float4*)bias,
            (float4*)out);
    } else {
        graphnorm_generic<<<n_graph, GTHREADS>>>(
            (const float4*)x, n_node,
            (const float4*)mean_scale, (const float4*)scale, (const float4*)bias,
            (float4*)out, nodes_per_graph);
    }
}